// round 12
// baseline (speedup 1.0000x reference)
#include <cuda_runtime.h>
#include <cuda_bf16.h>
#include <math.h>
#include <stdint.h>

#define BN_ 4096
#define KN_ 32
#define DN_ 256
#define DH_ 128
#define NREL_ 9
#define INV_T 14.285714285714286f
#define TS 40    // smem tile stride (32 + 8 pad)
#define TSK 136  // full-K smem stride (128 + 8 pad)

typedef __nv_bfloat16 bf16;

// ---------------- scratch (bf16 everywhere; fp32 accumulate inside MMA) ----------------
__device__ __align__(16) bf16 g_v1[BN_ * DN_];
__device__ __align__(16) bf16 g_v2[BN_ * DN_];
__device__ __align__(16) bf16 g_h1[BN_ * DN_];
__device__ __align__(16) bf16 g_h2[BN_ * DN_];
__device__ __align__(16) bf16 g_z1[BN_ * DH_];
__device__ __align__(16) bf16 g_z2[BN_ * DH_];
__device__ __align__(16) bf16 g_w1at[DN_ * DN_];
__device__ __align__(16) bf16 g_w1bt[DH_ * DN_];
__device__ __align__(16) bf16 g_w2at[DN_ * DN_];
__device__ __align__(16) bf16 g_w2bt[DH_ * DN_];
__device__ float g_rowsum[BN_];
__device__ float g_colsum[BN_];
__device__ float g_diag[BN_];
__device__ int   g_mask_u8;

// ---------------- prep: mask detect + zero + tiled weight transpose (bf16) ----------------
__global__ void prep_kernel(const float* __restrict__ W1a, const float* __restrict__ W1b,
                            const float* __restrict__ W2a, const float* __restrict__ W2b,
                            const unsigned int* __restrict__ m1) {
    int blk = blockIdx.x;
    int t = threadIdx.x;

    int zi = blk * 256 + t;
    if (zi < BN_) { g_rowsum[zi] = 0.f; g_colsum[zi] = 0.f; }

    __shared__ int sf;
    if (t == 0) sf = 0;
    __syncthreads();
    if (blk == 0) {
        int f = 0;
        for (int i = t; i < 4096; i += 256)
            if (m1[i] > 1u) f = 1;
        if (f) sf = 1;
    }
    __syncthreads();
    if (blk == 0 && t == 0) g_mask_u8 = sf;

    const float* W; bf16* Th; int N, tile;
    const int K = DN_;
    if (blk < 16)      { W = W1a; Th = g_w1at; N = 256; tile = blk; }
    else if (blk < 24) { W = W1b; Th = g_w1bt; N = 128; tile = blk - 16; }
    else if (blk < 40) { W = W2a; Th = g_w2at; N = 256; tile = blk - 24; }
    else               { W = W2b; Th = g_w2bt; N = 128; tile = blk - 40; }
    int tn = N / 64;
    int k0 = (tile / tn) * 64, n0 = (tile % tn) * 64;

    __shared__ float s[64][65];
#pragma unroll
    for (int i = 0; i < 16; i++) {
        int idx = t + i * 256;
        int r = idx >> 6, c = idx & 63;
        s[r][c] = W[(size_t)(k0 + r) * N + n0 + c];
    }
    __syncthreads();
#pragma unroll
    for (int i = 0; i < 16; i++) {
        int idx = t + i * 256;
        int n = idx >> 6, k = idx & 63;
        Th[(size_t)(n0 + n) * K + k0 + k] = __float2bfloat16(s[k][n]);
    }
}

// ---------------- aggregation: float4 row gather, 4 neighbor-groups ----------------
__global__ void aggregate_kernel(const float* __restrict__ nf,
                                 const float* __restrict__ rel,
                                 const int* __restrict__ nb1, const int* __restrict__ rl1, const void* __restrict__ m1,
                                 const int* __restrict__ nb2, const int* __restrict__ rl2, const void* __restrict__ m2,
                                 const int* __restrict__ selfids) {
    int b = blockIdx.x;
    const int* nb; const int* rl; const void* m; bf16* oh;
    if (b < BN_) { nb = nb1; rl = rl1; m = m1; oh = g_v1; }
    else         { b -= BN_; nb = nb2; rl = rl2; m = m2; oh = g_v2; }

    __shared__ int s_nb[KN_];
    __shared__ float s_rcnt[16];
    __shared__ int s_cnt;
    __shared__ __align__(16) float s_part[4 * 256];
    int t = threadIdx.x;
    if (t < 16) s_rcnt[t] = 0.f;
    __syncthreads();
    if (t < KN_) {
        int mk;
        if (g_mask_u8) mk = ((const unsigned char*)m)[b * KN_ + t];
        else           mk = ((const int*)m)[b * KN_ + t];
        mk = (mk != 0);
        int nbv = nb[b * KN_ + t];
        int rlv = rl[b * KN_ + t];
        unsigned bal = __ballot_sync(0xFFFFFFFFu, mk);
        if (mk) {
            int pos = __popc(bal & ((1u << t) - 1u));
            s_nb[pos] = nbv;
            atomicAdd(&s_rcnt[rlv], 1.f);
        }
        if (t == 0) s_cnt = __popc(bal);
    }
    __syncthreads();
    int cnt = s_cnt;

    int g = t >> 6, l64 = t & 63;
    float4 a0 = make_float4(0.f, 0.f, 0.f, 0.f);
    float4 a1 = make_float4(0.f, 0.f, 0.f, 0.f);
    int k = g;
    for (; k + 4 < cnt; k += 8) {
        float4 v0 = *((const float4*)(nf + (size_t)s_nb[k] * DN_) + l64);
        float4 v1 = *((const float4*)(nf + (size_t)s_nb[k + 4] * DN_) + l64);
        a0.x += v0.x; a0.y += v0.y; a0.z += v0.z; a0.w += v0.w;
        a1.x += v1.x; a1.y += v1.y; a1.z += v1.z; a1.w += v1.w;
    }
    if (k < cnt) {
        float4 v0 = *((const float4*)(nf + (size_t)s_nb[k] * DN_) + l64);
        a0.x += v0.x; a0.y += v0.y; a0.z += v0.z; a0.w += v0.w;
    }
    a0.x += a1.x; a0.y += a1.y; a0.z += a1.z; a0.w += a1.w;
    ((float4*)s_part)[g * 64 + l64] = a0;
    __syncthreads();

    int d = t;
    float acc = s_part[d] + s_part[256 + d] + s_part[512 + d] + s_part[768 + d];
#pragma unroll
    for (int r = 0; r < NREL_; r++)
        acc = fmaf(s_rcnt[r], rel[r * DN_ + d], acc);
    float res;
    if (cnt > 0) res = acc / (float)cnt;
    else         res = nf[(size_t)selfids[b] * DN_ + d];
    oh[(size_t)b * DN_ + d] = __float2bfloat16(res);
}

// ---------------- async-copy / ldmatrix / mma primitives ----------------
__device__ __forceinline__ void cp16(uint32_t s, const void* g) {
    asm volatile("cp.async.cg.shared.global [%0], [%1], 16;\n" :: "r"(s), "l"(g));
}
__device__ __forceinline__ void cpcommit() {
    asm volatile("cp.async.commit_group;\n" ::: "memory");
}
template <int N>
__device__ __forceinline__ void cpwait() {
    asm volatile("cp.async.wait_group %0;\n" :: "n"(N) : "memory");
}
__device__ __forceinline__ void ldsm4(unsigned r[4], uint32_t a) {
    asm volatile("ldmatrix.sync.aligned.m8n8.x4.shared.b16 {%0,%1,%2,%3}, [%4];\n"
                 : "=r"(r[0]), "=r"(r[1]), "=r"(r[2]), "=r"(r[3]) : "r"(a));
}
__device__ __forceinline__ void mma16816(float c[4], unsigned a0, unsigned a1, unsigned a2, unsigned a3,
                                         unsigned b0, unsigned b1) {
    asm volatile("mma.sync.aligned.m16n8k16.row.col.f32.bf16.bf16.f32 "
                 "{%0,%1,%2,%3}, {%4,%5,%6,%7}, {%8,%9}, {%0,%1,%2,%3};\n"
                 : "+f"(c[0]), "+f"(c[1]), "+f"(c[2]), "+f"(c[3])
                 : "r"(a0), "r"(a1), "r"(a2), "r"(a3), "r"(b0), "r"(b1));
}

// single-pass bf16 stage load: A BM rows + B BN rows, 32 k-cols
template <int BM, int BN>
__device__ __forceinline__ void issue_stage1(uint32_t sb,
        const bf16* A, const bf16* B, int bm, int bn, int ld, int k0, int tid) {
#pragma unroll
    for (int idx = tid; idx < BM * 4; idx += 256) {
        int row = idx >> 2, seg = idx & 3;
        cp16(sb + (uint32_t)(row * TS + seg * 8) * 2,
             A + (size_t)(bm + row) * ld + k0 + seg * 8);
    }
#pragma unroll
    for (int idx = tid; idx < BN * 4; idx += 256) {
        int row = idx >> 2, seg = idx & 3;
        cp16(sb + BM * TS * 2 + (uint32_t)(row * TS + seg * 8) * 2,
             B + (size_t)(bn + row) * ld + k0 + seg * 8);
    }
}

// 2-stage pipelined single-pass bf16 MMA mainloop
template <int BM, int BN, int MS, int NS, int WCOLS, int NIT>
__device__ __forceinline__ void mma_pipe1(float (&c)[MS][NS][4],
        const bf16* A, const bf16* B, int bm, int bn, int ld, char* smem_dyn, int tid) {
    constexpr int SSB = (BM + BN) * TS * 2;   // bytes per stage
    uint32_t sb0 = (uint32_t)__cvta_generic_to_shared(smem_dyn);
    int lane = tid & 31, w = tid >> 5;
    int wr = w / WCOLS, wc = w % WCOLS;
    int rowA = (lane & 7) + ((lane >> 3) & 1) * 8;
    int kA   = (lane >> 4) * 8;
    int rowB = (lane & 7) + (lane >> 4) * 8;
    int kB   = ((lane >> 3) & 1) * 8;

    issue_stage1<BM, BN>(sb0, A, B, bm, bn, ld, 0, tid);
    cpcommit();

#pragma unroll 1
    for (int it = 0; it < NIT; ++it) {
        uint32_t scur = sb0 + (it & 1) * SSB;
        if (it + 1 < NIT) {
            issue_stage1<BM, BN>(sb0 + ((it + 1) & 1) * SSB, A, B, bm, bn, ld, (it + 1) * 32, tid);
            cpcommit();
            cpwait<1>();
        } else {
            cpwait<0>();
        }
        __syncthreads();
        uint32_t sA_ = scur;
        uint32_t sB_ = scur + BM * TS * 2;
#pragma unroll
        for (int kk = 0; kk < 32; kk += 16) {
            unsigned a[MS][4];
#pragma unroll
            for (int ms = 0; ms < MS; ms++)
                ldsm4(a[ms], sA_ + (uint32_t)(((wr * MS + ms) * 16 + rowA) * TS + kk + kA) * 2);
            unsigned bfrag[NS][2];
#pragma unroll
            for (int np = 0; np < NS / 2; np++) {
                unsigned r[4];
                ldsm4(r, sB_ + (uint32_t)((wc * NS * 8 + np * 16 + rowB) * TS + kk + kB) * 2);
                bfrag[2 * np][0] = r[0]; bfrag[2 * np][1] = r[1];
                bfrag[2 * np + 1][0] = r[2]; bfrag[2 * np + 1][1] = r[3];
            }
#pragma unroll
            for (int ms = 0; ms < MS; ms++)
#pragma unroll
                for (int ns = 0; ns < NS; ns++)
                    mma16816(c[ms][ns], a[ms][0], a[ms][1], a[ms][2], a[ms][3], bfrag[ns][0], bfrag[ns][1]);
        }
        __syncthreads();
    }
}

// ---------------- proj-a: 128x64 tiles, grid (32,4,2) ----------------
__global__ void __launch_bounds__(256, 3) mma_projA_kernel(
        const float* __restrict__ b1a, const float* __restrict__ b2a) {
    extern __shared__ char smem_dyn[];
    int tid = threadIdx.x;
    int lane = tid & 31, w = tid >> 5;
    int wr = w >> 1, wc = w & 1;
    int grp = lane >> 2, qp = (lane & 3) * 2;
    int bm = blockIdx.x * 128, bn = blockIdx.y * 64;
    int view = blockIdx.z;
    const bf16* A = view ? g_v2 : g_v1;
    const bf16* B = view ? g_w2at : g_w1at;
    const float* bias = view ? b2a : b1a;
    bf16* C = view ? g_h2 : g_h1;

    float c[2][4][4] = {};
    mma_pipe1<128, 64, 2, 4, 2, 8>(c, A, B, bm, bn, DN_, smem_dyn, tid);

#pragma unroll
    for (int ms = 0; ms < 2; ms++) {
#pragma unroll
        for (int ns = 0; ns < 4; ns++) {
            int col = bn + wc * 32 + ns * 8 + qp;
            float b0 = bias[col], b1 = bias[col + 1];
#pragma unroll
            for (int h = 0; h < 2; h++) {
                int row = bm + (wr * 2 + ms) * 16 + grp + 8 * h;
                float v0 = fmaxf(c[ms][ns][2 * h + 0] + b0, 0.f);
                float v1 = fmaxf(c[ms][ns][2 * h + 1] + b1, 0.f);
                __nv_bfloat162 hp;
                hp.x = __float2bfloat16(v0); hp.y = __float2bfloat16(v1);
                *(__nv_bfloat162*)(C + (size_t)row * DN_ + col) = hp;
            }
        }
    }
}

// ---------------- proj-b: 32x128 tiles + fused L2-normalize, grid (128,1,2) ----------------
__global__ void __launch_bounds__(256, 3) mma_projB_kernel(
        const float* __restrict__ b1b, const float* __restrict__ b2b) {
    extern __shared__ char smem_dyn[];
    __shared__ float s_ss[32];
    int tid = threadIdx.x;
    int lane = tid & 31, w = tid >> 5;
    int wr = w >> 2, wc = w & 3;
    int grp = lane >> 2, qp = (lane & 3) * 2;
    int bm = blockIdx.x * 32;
    int view = blockIdx.z;
    const bf16* A = view ? g_h2 : g_h1;
    const bf16* B = view ? g_w2bt : g_w1bt;
    const float* bias = view ? b2b : b1b;
    bf16* Z = view ? g_z2 : g_z1;

    if (tid < 32) s_ss[tid] = 0.f;

    float c[1][4][4] = {};
    mma_pipe1<32, 128, 1, 4, 4, 8>(c, A, B, bm, 0, DN_, smem_dyn, tid);

    float vv[4][4];
#pragma unroll
    for (int ns = 0; ns < 4; ns++) {
        int col = wc * 32 + ns * 8 + qp;
        float b0 = bias[col], b1 = bias[col + 1];
#pragma unroll
        for (int h = 0; h < 2; h++) {
            vv[ns][2 * h + 0] = c[0][ns][2 * h + 0] + b0;
            vv[ns][2 * h + 1] = c[0][ns][2 * h + 1] + b1;
        }
    }
#pragma unroll
    for (int h = 0; h < 2; h++) {
        float ss = 0.f;
#pragma unroll
        for (int ns = 0; ns < 4; ns++) {
            float a = vv[ns][2 * h + 0], b = vv[ns][2 * h + 1];
            ss = fmaf(a, a, ss); ss = fmaf(b, b, ss);
        }
        ss += __shfl_xor_sync(0xFFFFFFFFu, ss, 1);
        ss += __shfl_xor_sync(0xFFFFFFFFu, ss, 2);
        if ((lane & 3) == 0)
            atomicAdd(&s_ss[wr * 16 + grp + 8 * h], ss);
    }
    __syncthreads();

#pragma unroll
    for (int h = 0; h < 2; h++) {
        int rloc = wr * 16 + grp + 8 * h;
        float rinv = rsqrtf(s_ss[rloc]);
        int row = bm + rloc;
#pragma unroll
        for (int ns = 0; ns < 4; ns++) {
            int col = wc * 32 + ns * 8 + qp;
            float v0 = vv[ns][2 * h + 0] * rinv;
            float v1 = vv[ns][2 * h + 1] * rinv;
            __nv_bfloat162 hp;
            hp.x = __float2bfloat16(v0); hp.y = __float2bfloat16(v1);
            *(__nv_bfloat162*)(Z + (size_t)row * DH_ + col) = hp;
        }
    }
}

// ---------------- sim: bf16 single-stage GEMM + shifted-exp LSE, grid (32,32) ----------------
__global__ void __launch_bounds__(256, 2) sim_lse_kernel() {
    extern __shared__ char smem_dyn[];
    __shared__ float s_rs[128], s_cs[128];
    int tid = threadIdx.x;
    int lane = tid & 31, w = tid >> 5;
    int wr = w >> 2, wc = w & 3;
    int grp = lane >> 2, qp = (lane & 3) * 2;
    int bm = blockIdx.x * 128, bn = blockIdx.y * 128;
    if (tid < 128) { s_rs[tid] = 0.f; s_cs[tid] = 0.f; }

    uint32_t sA = (uint32_t)__cvta_generic_to_shared(smem_dyn);
    uint32_t sB = sA + 128 * TSK * 2;

#pragma unroll
    for (int i = 0; i < 8; i++) {
        int idx = tid + i * 256;
        int row = idx >> 4, seg = idx & 15;
        uint32_t so = (uint32_t)(row * TSK + seg * 8) * 2;
        cp16(sA + so, g_z1 + (size_t)(bm + row) * DH_ + seg * 8);
        cp16(sB + so, g_z2 + (size_t)(bn + row) * DH_ + seg * 8);
    }
    cpcommit();
    cpwait<0>();
    __syncthreads();

    int rowA = (lane & 7) + ((lane >> 3) & 1) * 8;
    int kA   = (lane >> 4) * 8;
    int rowB = (lane & 7) + (lane >> 4) * 8;
    int kB   = ((lane >> 3) & 1) * 8;

    float c[4][4][4] = {};
#pragma unroll
    for (int kk = 0; kk < 128; kk += 16) {
        unsigned a[4][4];
#pragma unroll
        for (int ms = 0; ms < 4; ms++)
            ldsm4(a[ms], sA + (uint32_t)(((wr * 4 + ms) * 16 + rowA) * TSK + kk + kA) * 2);
        unsigned bfr[4][2];
#pragma unroll
        for (int np = 0; np < 2; np++) {
            unsigned r[4];
            ldsm4(r, sB + (uint32_t)((wc * 32 + np * 16 + rowB) * TSK + kk + kB) * 2);
            bfr[2 * np][0] = r[0]; bfr[2 * np][1] = r[1];
            bfr[2 * np + 1][0] = r[2]; bfr[2 * np + 1][1] = r[3];
        }
#pragma unroll
        for (int ms = 0; ms < 4; ms++)
#pragma unroll
            for (int ns = 0; ns < 4; ns++)
                mma16816(c[ms][ns], a[ms][0], a[ms][1], a[ms][2], a[ms][3], bfr[ns][0], bfr[ns][1]);
    }

    float rs[4][2] = {}, cs[4][2] = {};
#pragma unroll
    for (int ms = 0; ms < 4; ms++) {
#pragma unroll
        for (int ns = 0; ns < 4; ns++) {
#pragma unroll
            for (int r = 0; r < 4; r++) {
                int h = r >> 1, p = r & 1;
                int row = bm + (wr * 4 + ms) * 16 + grp + 8 * h;
                int col = bn + wc * 32 + ns * 8 + qp + p;
                float s = c[ms][ns][r] * INV_T;
                if (row == col) g_diag[row] = s;
                float ev = __expf(s - INV_T);
                rs[ms][h] += ev;
                cs[ns][p] += ev;
            }
        }
    }
#pragma unroll
    for (int ms = 0; ms < 4; ms++)
#pragma unroll
        for (int h = 0; h < 2; h++) {
            float v = rs[ms][h];
            v += __shfl_xor_sync(0xFFFFFFFFu, v, 1);
            v += __shfl_xor_sync(0xFFFFFFFFu, v, 2);
            if ((lane & 3) == 0)
                atomicAdd(&s_rs[(wr * 4 + ms) * 16 + grp + 8 * h], v);
        }
#pragma unroll
    for (int ns = 0; ns < 4; ns++)
#pragma unroll
        for (int p = 0; p < 2; p++) {
            float v = cs[ns][p];
            v += __shfl_xor_sync(0xFFFFFFFFu, v, 4);
            v += __shfl_xor_sync(0xFFFFFFFFu, v, 8);
            v += __shfl_xor_sync(0xFFFFFFFFu, v, 16);
            if (grp == 0)
                atomicAdd(&s_cs[wc * 32 + ns * 8 + qp + p], v);
        }
    __syncthreads();
    if (tid < 128) {
        atomicAdd(&g_rowsum[bm + tid], s_rs[tid]);
        atomicAdd(&g_colsum[bn + tid], s_cs[tid]);
    }
}

// ---------------- final loss reduce ----------------
__global__ void loss_kernel(float* __restrict__ out) {
    float acc = 0.f;
    for (int i = threadIdx.x; i < BN_; i += 256) {
        acc += 0.5f * (logf(g_rowsum[i]) + logf(g_colsum[i])) + INV_T - g_diag[i];
    }
#pragma unroll
    for (int off = 16; off; off >>= 1) acc += __shfl_xor_sync(0xFFFFFFFFu, acc, off);
    __shared__ float wsum[8];
    if ((threadIdx.x & 31) == 0) wsum[threadIdx.x >> 5] = acc;
    __syncthreads();
    if (threadIdx.x == 0) {
        float tot = 0.f;
        for (int k = 0; k < 8; k++) tot += wsum[k];
        out[0] = tot / (float)BN_;
    }
}

// ---------------- launch ----------------
extern "C" void kernel_launch(void* const* d_in, const int* in_sizes, int n_in,
                              void* d_out, int out_size) {
    const float* nf   = (const float*)d_in[0];
    const float* rel  = (const float*)d_in[1];
    const int*   nb1  = (const int*)d_in[2];
    const int*   rl1  = (const int*)d_in[3];
    const void*  m1   = d_in[4];
    const int*   nb2  = (const int*)d_in[5];
    const int*   rl2  = (const int*)d_in[6];
    const void*  m2   = d_in[7];
    const int*   self_ = (const int*)d_in[8];
    const float* W1a  = (const float*)d_in[9];
    const float* b1a  = (const float*)d_in[10];
    const float* W1b  = (const float*)d_in[11];
    const float* b1b  = (const float*)d_in[12];
    const float* W2a  = (const float*)d_in[13];
    const float* b2a  = (const float*)d_in[14];
    const float* W2b  = (const float*)d_in[15];
    const float* b2b  = (const float*)d_in[16];

    const int smemA  = (128 + 64) * TS * 2 * 2;   // 30720
    const int smemB  = (32 + 128) * TS * 2 * 2;   // 25600
    const int smemS  = 2 * 128 * TSK * 2;         // 69632
    cudaFuncSetAttribute(mma_projA_kernel, cudaFuncAttributeMaxDynamicSharedMemorySize, smemA);
    cudaFuncSetAttribute(mma_projB_kernel, cudaFuncAttributeMaxDynamicSharedMemorySize, smemB);
    cudaFuncSetAttribute(sim_lse_kernel,   cudaFuncAttributeMaxDynamicSharedMemorySize, smemS);

    prep_kernel<<<48, 256>>>(W1a, W1b, W2a, W2b, (const unsigned int*)m1);
    aggregate_kernel<<<2 * BN_, 256>>>(nf, rel, nb1, rl1, m1, nb2, rl2, m2, self_);
    mma_projA_kernel<<<dim3(32, 4, 2), 256, smemA>>>(b1a, b2a);
    mma_projB_kernel<<<dim3(128, 1, 2), 256, smemB>>>(b1b, b2b);
    sim_lse_kernel<<<dim3(32, 32), 256, smemS>>>();
    loss_kernel<<<1, 256>>>((float*)d_out);
}

// round 13
// speedup vs baseline: 1.4261x; 1.4261x over previous
#include <cuda_runtime.h>
#include <cuda_bf16.h>
#include <math.h>
#include <stdint.h>

#define BN_ 4096
#define KN_ 32
#define DN_ 256
#define DH_ 128
#define NREL_ 9
#define INV_T 14.285714285714286f
#define TSK 136  // sim smem stride (128 + 8 pad)
#define TSF 264  // fused-proj smem stride for K=256 rows (256 + 8 pad)

typedef __nv_bfloat16 bf16;

// ---------------- scratch ----------------
__device__ __align__(16) bf16 g_v1[BN_ * DN_];
__device__ __align__(16) bf16 g_v2[BN_ * DN_];
__device__ __align__(16) bf16 g_z1[BN_ * DH_];
__device__ __align__(16) bf16 g_z2[BN_ * DH_];
__device__ __align__(16) bf16 g_w1at[DN_ * DN_];
__device__ __align__(16) bf16 g_w1bt[DH_ * DN_];
__device__ __align__(16) bf16 g_w2at[DN_ * DN_];
__device__ __align__(16) bf16 g_w2bt[DH_ * DN_];
__device__ float g_rowsum[BN_];
__device__ float g_colsum[BN_];
__device__ float g_diag[BN_];
__device__ int   g_mask_u8;

// ---------------- prep: mask detect + zero + tiled weight transpose (bf16) ----------------
__global__ void prep_kernel(const float* __restrict__ W1a, const float* __restrict__ W1b,
                            const float* __restrict__ W2a, const float* __restrict__ W2b,
                            const unsigned int* __restrict__ m1) {
    int blk = blockIdx.x;
    int t = threadIdx.x;

    int zi = blk * 256 + t;
    if (zi < BN_) { g_rowsum[zi] = 0.f; g_colsum[zi] = 0.f; }

    __shared__ int sf;
    if (t == 0) sf = 0;
    __syncthreads();
    if (blk == 0) {
        int f = 0;
        for (int i = t; i < 4096; i += 256)
            if (m1[i] > 1u) f = 1;
        if (f) sf = 1;
    }
    __syncthreads();
    if (blk == 0 && t == 0) g_mask_u8 = sf;

    const float* W; bf16* Th; int N, tile;
    const int K = DN_;
    if (blk < 16)      { W = W1a; Th = g_w1at; N = 256; tile = blk; }
    else if (blk < 24) { W = W1b; Th = g_w1bt; N = 128; tile = blk - 16; }
    else if (blk < 40) { W = W2a; Th = g_w2at; N = 256; tile = blk - 24; }
    else               { W = W2b; Th = g_w2bt; N = 128; tile = blk - 40; }
    int tn = N / 64;
    int k0 = (tile / tn) * 64, n0 = (tile % tn) * 64;

    __shared__ float s[64][65];
#pragma unroll
    for (int i = 0; i < 16; i++) {
        int idx = t + i * 256;
        int r = idx >> 6, c = idx & 63;
        s[r][c] = W[(size_t)(k0 + r) * N + n0 + c];
    }
    __syncthreads();
#pragma unroll
    for (int i = 0; i < 16; i++) {
        int idx = t + i * 256;
        int n = idx >> 6, k = idx & 63;
        Th[(size_t)(n0 + n) * K + k0 + k] = __float2bfloat16(s[k][n]);
    }
}

// ---------------- aggregation: float4 row gather, 4 neighbor-groups ----------------
__global__ void aggregate_kernel(const float* __restrict__ nf,
                                 const float* __restrict__ rel,
                                 const int* __restrict__ nb1, const int* __restrict__ rl1, const void* __restrict__ m1,
                                 const int* __restrict__ nb2, const int* __restrict__ rl2, const void* __restrict__ m2,
                                 const int* __restrict__ selfids) {
    int b = blockIdx.x;
    const int* nb; const int* rl; const void* m; bf16* oh;
    if (b < BN_) { nb = nb1; rl = rl1; m = m1; oh = g_v1; }
    else         { b -= BN_; nb = nb2; rl = rl2; m = m2; oh = g_v2; }

    __shared__ int s_nb[KN_];
    __shared__ float s_rcnt[16];
    __shared__ int s_cnt;
    __shared__ __align__(16) float s_part[4 * 256];
    int t = threadIdx.x;
    if (t < 16) s_rcnt[t] = 0.f;
    __syncthreads();
    if (t < KN_) {
        int mk;
        if (g_mask_u8) mk = ((const unsigned char*)m)[b * KN_ + t];
        else           mk = ((const int*)m)[b * KN_ + t];
        mk = (mk != 0);
        int nbv = nb[b * KN_ + t];
        int rlv = rl[b * KN_ + t];
        unsigned bal = __ballot_sync(0xFFFFFFFFu, mk);
        if (mk) {
            int pos = __popc(bal & ((1u << t) - 1u));
            s_nb[pos] = nbv;
            atomicAdd(&s_rcnt[rlv], 1.f);
        }
        if (t == 0) s_cnt = __popc(bal);
    }
    __syncthreads();
    int cnt = s_cnt;

    int g = t >> 6, l64 = t & 63;
    float4 a0 = make_float4(0.f, 0.f, 0.f, 0.f);
    float4 a1 = make_float4(0.f, 0.f, 0.f, 0.f);
    int k = g;
    for (; k + 4 < cnt; k += 8) {
        float4 v0 = *((const float4*)(nf + (size_t)s_nb[k] * DN_) + l64);
        float4 v1 = *((const float4*)(nf + (size_t)s_nb[k + 4] * DN_) + l64);
        a0.x += v0.x; a0.y += v0.y; a0.z += v0.z; a0.w += v0.w;
        a1.x += v1.x; a1.y += v1.y; a1.z += v1.z; a1.w += v1.w;
    }
    if (k < cnt) {
        float4 v0 = *((const float4*)(nf + (size_t)s_nb[k] * DN_) + l64);
        a0.x += v0.x; a0.y += v0.y; a0.z += v0.z; a0.w += v0.w;
    }
    a0.x += a1.x; a0.y += a1.y; a0.z += a1.z; a0.w += a1.w;
    ((float4*)s_part)[g * 64 + l64] = a0;
    __syncthreads();

    int d = t;
    float acc = s_part[d] + s_part[256 + d] + s_part[512 + d] + s_part[768 + d];
#pragma unroll
    for (int r = 0; r < NREL_; r++)
        acc = fmaf(s_rcnt[r], rel[r * DN_ + d], acc);
    float res;
    if (cnt > 0) res = acc / (float)cnt;
    else         res = nf[(size_t)selfids[b] * DN_ + d];
    oh[(size_t)b * DN_ + d] = __float2bfloat16(res);
}

// ---------------- async-copy / ldmatrix / mma primitives ----------------
__device__ __forceinline__ void cp16(uint32_t s, const void* g) {
    asm volatile("cp.async.cg.shared.global [%0], [%1], 16;\n" :: "r"(s), "l"(g));
}
__device__ __forceinline__ void cpcommit() {
    asm volatile("cp.async.commit_group;\n" ::: "memory");
}
template <int N>
__device__ __forceinline__ void cpwait() {
    asm volatile("cp.async.wait_group %0;\n" :: "n"(N) : "memory");
}
__device__ __forceinline__ void ldsm4(unsigned r[4], uint32_t a) {
    asm volatile("ldmatrix.sync.aligned.m8n8.x4.shared.b16 {%0,%1,%2,%3}, [%4];\n"
                 : "=r"(r[0]), "=r"(r[1]), "=r"(r[2]), "=r"(r[3]) : "r"(a));
}
__device__ __forceinline__ void mma16816(float c[4], unsigned a0, unsigned a1, unsigned a2, unsigned a3,
                                         unsigned b0, unsigned b1) {
    asm volatile("mma.sync.aligned.m16n8k16.row.col.f32.bf16.bf16.f32 "
                 "{%0,%1,%2,%3}, {%4,%5,%6,%7}, {%8,%9}, {%0,%1,%2,%3};\n"
                 : "+f"(c[0]), "+f"(c[1]), "+f"(c[2]), "+f"(c[3])
                 : "r"(a0), "r"(a1), "r"(a2), "r"(a3), "r"(b0), "r"(b1));
}

// ---------------- fused proj: h = relu(v@Wa^T+ba); z = normalize(h@Wb^T+bb) ----------------
// Per CTA: 64 M-rows, one view. smem: sV(64x256) + sH(64x256) + 2 x sW(64x256) chunks.
// Warp layout: 8 warps, wr = w>>1 (4 M-strips of 16), wc = w&1 (2 N-strips of 32).
#define SV_OFF 0
#define SH_OFF 33792
#define SW0_OFF 67584
#define SW1_OFF 101376
#define FPROJ_SMEM 135168

__device__ __forceinline__ void load_rows64(uint32_t sdst, const bf16* gsrc, int tid) {
#pragma unroll
    for (int i = 0; i < 8; i++) {
        int e = tid + i * 256;
        int row = e >> 5, seg = e & 31;
        cp16(sdst + (uint32_t)(row * TSF + seg * 8) * 2, gsrc + (size_t)row * DN_ + seg * 8);
    }
}

__global__ void __launch_bounds__(256, 1) fused_proj_kernel(
        const float* __restrict__ b1a, const float* __restrict__ b2a,
        const float* __restrict__ b1b, const float* __restrict__ b2b) {
    extern __shared__ char smem_dyn[];
    __shared__ float s_ss[64];
    uint32_t sb = (uint32_t)__cvta_generic_to_shared(smem_dyn);
    uint32_t sV = sb + SV_OFF, sH = sb + SH_OFF;
    uint32_t sW[2] = { sb + SW0_OFF, sb + SW1_OFF };

    int tid = threadIdx.x;
    int lane = tid & 31, w = tid >> 5;
    int wr = w >> 1, wc = w & 1;
    int grp = lane >> 2, qp = (lane & 3) * 2;
    int bm = blockIdx.x * 64;
    int view = blockIdx.z;
    const bf16* V  = view ? g_v2 : g_v1;
    const bf16* Wa = view ? g_w2at : g_w1at;
    const bf16* Wb = view ? g_w2bt : g_w1bt;
    const float* ba = view ? b2a : b1a;
    const float* bb = view ? b2b : b1b;
    bf16* Z = view ? g_z2 : g_z1;

    if (tid < 64) s_ss[tid] = 0.f;

    // ldmatrix lane decomposition
    int rowA = (lane & 7) + ((lane >> 3) & 1) * 8;
    int kA   = (lane >> 4) * 8;
    int rowB = (lane & 7) + (lane >> 4) * 8;
    int kB   = ((lane >> 3) & 1) * 8;

    // preload v tile + Wa chunk 0 (group 0)
    load_rows64(sV, V + (size_t)bm * DN_, tid);
    load_rows64(sW[0], Wa, tid);
    cpcommit();

    float c2[2][4][4] = {};   // phase-2 accumulators (persist across chunks)

    // -------- phase 1: h = relu(v @ Wa^T + ba), 4 chunks of 64 N-cols --------
#pragma unroll 1
    for (int c = 0; c < 4; c++) {
        cpwait<0>();
        __syncthreads();
        // prefetch next chunk into the other buffer (Wa c+1, or Wb chunk 0)
        if (c < 3)      load_rows64(sW[(c + 1) & 1], Wa + (size_t)(c + 1) * 64 * DN_, tid);
        else            load_rows64(sW[(c + 1) & 1], Wb, tid);
        cpcommit();

        uint32_t sWc = sW[c & 1];
        float c1[4][4] = {};
#pragma unroll
        for (int kk = 0; kk < 256; kk += 16) {
            unsigned a[4];
            ldsm4(a, sV + (uint32_t)((wr * 16 + rowA) * TSF + kk + kA) * 2);
            unsigned bfrag[4][2];
#pragma unroll
            for (int np = 0; np < 2; np++) {
                unsigned r[4];
                ldsm4(r, sWc + (uint32_t)((wc * 32 + np * 16 + rowB) * TSF + kk + kB) * 2);
                bfrag[2 * np][0] = r[0]; bfrag[2 * np][1] = r[1];
                bfrag[2 * np + 1][0] = r[2]; bfrag[2 * np + 1][1] = r[3];
            }
#pragma unroll
            for (int ns = 0; ns < 4; ns++)
                mma16816(c1[ns], a[0], a[1], a[2], a[3], bfrag[ns][0], bfrag[ns][1]);
        }
        // epilogue: bias + relu -> sH (bf16) at cols c*64..
#pragma unroll
        for (int ns = 0; ns < 4; ns++) {
            int col = c * 64 + wc * 32 + ns * 8 + qp;
            float bias0 = ba[col], bias1 = ba[col + 1];
#pragma unroll
            for (int h = 0; h < 2; h++) {
                int row = wr * 16 + grp + 8 * h;
                float v0 = fmaxf(c1[ns][2 * h + 0] + bias0, 0.f);
                float v1 = fmaxf(c1[ns][2 * h + 1] + bias1, 0.f);
                __nv_bfloat162 hp;
                hp.x = __float2bfloat16(v0); hp.y = __float2bfloat16(v1);
                *(__nv_bfloat162*)(smem_dyn + SH_OFF + (size_t)(row * TSF + col) * 2) = hp;
            }
        }
    }

    // -------- phase 2: z = h @ Wb^T + bb, 2 chunks of 64 N-cols --------
#pragma unroll 1
    for (int c = 0; c < 2; c++) {
        cpwait<0>();
        __syncthreads();   // also orders sH writes before reads
        if (c < 1) { load_rows64(sW[(4 + c + 1) & 1], Wb + (size_t)64 * DN_, tid); cpcommit(); }

        uint32_t sWc = sW[(4 + c) & 1];
#pragma unroll
        for (int kk = 0; kk < 256; kk += 16) {
            unsigned a[4];
            ldsm4(a, sH + (uint32_t)((wr * 16 + rowA) * TSF + kk + kA) * 2);
            unsigned bfrag[4][2];
#pragma unroll
            for (int np = 0; np < 2; np++) {
                unsigned r[4];
                ldsm4(r, sWc + (uint32_t)((wc * 32 + np * 16 + rowB) * TSF + kk + kB) * 2);
                bfrag[2 * np][0] = r[0]; bfrag[2 * np][1] = r[1];
                bfrag[2 * np + 1][0] = r[2]; bfrag[2 * np + 1][1] = r[3];
            }
#pragma unroll
            for (int ns = 0; ns < 4; ns++)
                mma16816(c2[c][ns], a[0], a[1], a[2], a[3], bfrag[ns][0], bfrag[ns][1]);
        }
    }

    // bias + sum-of-squares across both chunks
    float vv[2][4][4];
#pragma unroll
    for (int c = 0; c < 2; c++)
#pragma unroll
        for (int ns = 0; ns < 4; ns++) {
            int col = c * 64 + wc * 32 + ns * 8 + qp;
            float bias0 = bb[col], bias1 = bb[col + 1];
#pragma unroll
            for (int h = 0; h < 2; h++) {
                vv[c][ns][2 * h + 0] = c2[c][ns][2 * h + 0] + bias0;
                vv[c][ns][2 * h + 1] = c2[c][ns][2 * h + 1] + bias1;
            }
        }
#pragma unroll
    for (int h = 0; h < 2; h++) {
        float ss = 0.f;
#pragma unroll
        for (int c = 0; c < 2; c++)
#pragma unroll
            for (int ns = 0; ns < 4; ns++) {
                float a = vv[c][ns][2 * h + 0], b = vv[c][ns][2 * h + 1];
                ss = fmaf(a, a, ss); ss = fmaf(b, b, ss);
            }
        ss += __shfl_xor_sync(0xFFFFFFFFu, ss, 1);
        ss += __shfl_xor_sync(0xFFFFFFFFu, ss, 2);
        if ((lane & 3) == 0)
            atomicAdd(&s_ss[wr * 16 + grp + 8 * h], ss);
    }
    __syncthreads();

#pragma unroll
    for (int h = 0; h < 2; h++) {
        int rloc = wr * 16 + grp + 8 * h;
        float rinv = rsqrtf(s_ss[rloc]);
        int row = bm + rloc;
#pragma unroll
        for (int c = 0; c < 2; c++)
#pragma unroll
            for (int ns = 0; ns < 4; ns++) {
                int col = c * 64 + wc * 32 + ns * 8 + qp;
                float v0 = vv[c][ns][2 * h + 0] * rinv;
                float v1 = vv[c][ns][2 * h + 1] * rinv;
                __nv_bfloat162 hp;
                hp.x = __float2bfloat16(v0); hp.y = __float2bfloat16(v1);
                *(__nv_bfloat162*)(Z + (size_t)row * DH_ + col) = hp;
            }
    }
}

// ---------------- sim: bf16 single-stage GEMM + shifted-exp LSE, grid (32,32) ----------------
__global__ void __launch_bounds__(256, 2) sim_lse_kernel() {
    extern __shared__ char smem_dyn[];
    __shared__ float s_rs[128], s_cs[128];
    int tid = threadIdx.x;
    int lane = tid & 31, w = tid >> 5;
    int wr = w >> 2, wc = w & 3;
    int grp = lane >> 2, qp = (lane & 3) * 2;
    int bm = blockIdx.x * 128, bn = blockIdx.y * 128;
    if (tid < 128) { s_rs[tid] = 0.f; s_cs[tid] = 0.f; }

    uint32_t sA = (uint32_t)__cvta_generic_to_shared(smem_dyn);
    uint32_t sB = sA + 128 * TSK * 2;

#pragma unroll
    for (int i = 0; i < 8; i++) {
        int idx = tid + i * 256;
        int row = idx >> 4, seg = idx & 15;
        uint32_t so = (uint32_t)(row * TSK + seg * 8) * 2;
        cp16(sA + so, g_z1 + (size_t)(bm + row) * DH_ + seg * 8);
        cp16(sB + so, g_z2 + (size_t)(bn + row) * DH_ + seg * 8);
    }
    cpcommit();
    cpwait<0>();
    __syncthreads();

    int rowA = (lane & 7) + ((lane >> 3) & 1) * 8;
    int kA   = (lane >> 4) * 8;
    int rowB = (lane & 7) + (lane >> 4) * 8;
    int kB   = ((lane >> 3) & 1) * 8;

    float c[4][4][4] = {};
#pragma unroll
    for (int kk = 0; kk < 128; kk += 16) {
        unsigned a[4][4];
#pragma unroll
        for (int ms = 0; ms < 4; ms++)
            ldsm4(a[ms], sA + (uint32_t)(((wr * 4 + ms) * 16 + rowA) * TSK + kk + kA) * 2);
        unsigned bfr[4][2];
#pragma unroll
        for (int np = 0; np < 2; np++) {
            unsigned r[4];
            ldsm4(r, sB + (uint32_t)((wc * 32 + np * 16 + rowB) * TSK + kk + kB) * 2);
            bfr[2 * np][0] = r[0]; bfr[2 * np][1] = r[1];
            bfr[2 * np + 1][0] = r[2]; bfr[2 * np + 1][1] = r[3];
        }
#pragma unroll
        for (int ms = 0; ms < 4; ms++)
#pragma unroll
            for (int ns = 0; ns < 4; ns++)
                mma16816(c[ms][ns], a[ms][0], a[ms][1], a[ms][2], a[ms][3], bfr[ns][0], bfr[ns][1]);
    }

    float rs[4][2] = {}, cs[4][2] = {};
#pragma unroll
    for (int ms = 0; ms < 4; ms++) {
#pragma unroll
        for (int ns = 0; ns < 4; ns++) {
#pragma unroll
            for (int r = 0; r < 4; r++) {
                int h = r >> 1, p = r & 1;
                int row = bm + (wr * 4 + ms) * 16 + grp + 8 * h;
                int col = bn + wc * 32 + ns * 8 + qp + p;
                float s = c[ms][ns][r] * INV_T;
                if (row == col) g_diag[row] = s;
                float ev = __expf(s - INV_T);
                rs[ms][h] += ev;
                cs[ns][p] += ev;
            }
        }
    }
#pragma unroll
    for (int ms = 0; ms < 4; ms++)
#pragma unroll
        for (int h = 0; h < 2; h++) {
            float v = rs[ms][h];
            v += __shfl_xor_sync(0xFFFFFFFFu, v, 1);
            v += __shfl_xor_sync(0xFFFFFFFFu, v, 2);
            if ((lane & 3) == 0)
                atomicAdd(&s_rs[(wr * 4 + ms) * 16 + grp + 8 * h], v);
        }
#pragma unroll
    for (int ns = 0; ns < 4; ns++)
#pragma unroll
        for (int p = 0; p < 2; p++) {
            float v = cs[ns][p];
            v += __shfl_xor_sync(0xFFFFFFFFu, v, 4);
            v += __shfl_xor_sync(0xFFFFFFFFu, v, 8);
            v += __shfl_xor_sync(0xFFFFFFFFu, v, 16);
            if (grp == 0)
                atomicAdd(&s_cs[wc * 32 + ns * 8 + qp + p], v);
        }
    __syncthreads();
    if (tid < 128) {
        atomicAdd(&g_rowsum[bm + tid], s_rs[tid]);
        atomicAdd(&g_colsum[bn + tid], s_cs[tid]);
    }
}

// ---------------- final loss reduce ----------------
__global__ void loss_kernel(float* __restrict__ out) {
    float acc = 0.f;
    for (int i = threadIdx.x; i < BN_; i += 256) {
        acc += 0.5f * (logf(g_rowsum[i]) + logf(g_colsum[i])) + INV_T - g_diag[i];
    }
#pragma unroll
    for (int off = 16; off; off >>= 1) acc += __shfl_xor_sync(0xFFFFFFFFu, acc, off);
    __shared__ float wsum[8];
    if ((threadIdx.x & 31) == 0) wsum[threadIdx.x >> 5] = acc;
    __syncthreads();
    if (threadIdx.x == 0) {
        float tot = 0.f;
        for (int k = 0; k < 8; k++) tot += wsum[k];
        out[0] = tot / (float)BN_;
    }
}

// ---------------- launch ----------------
extern "C" void kernel_launch(void* const* d_in, const int* in_sizes, int n_in,
                              void* d_out, int out_size) {
    const float* nf   = (const float*)d_in[0];
    const float* rel  = (const float*)d_in[1];
    const int*   nb1  = (const int*)d_in[2];
    const int*   rl1  = (const int*)d_in[3];
    const void*  m1   = d_in[4];
    const int*   nb2  = (const int*)d_in[5];
    const int*   rl2  = (const int*)d_in[6];
    const void*  m2   = d_in[7];
    const int*   self_ = (const int*)d_in[8];
    const float* W1a  = (const float*)d_in[9];
    const float* b1a  = (const float*)d_in[10];
    const float* W1b  = (const float*)d_in[11];
    const float* b1b  = (const float*)d_in[12];
    const float* W2a  = (const float*)d_in[13];
    const float* b2a  = (const float*)d_in[14];
    const float* W2b  = (const float*)d_in[15];
    const float* b2b  = (const float*)d_in[16];

    const int smemS = 2 * 128 * TSK * 2;   // 69632
    cudaFuncSetAttribute(fused_proj_kernel, cudaFuncAttributeMaxDynamicSharedMemorySize, FPROJ_SMEM);
    cudaFuncSetAttribute(sim_lse_kernel,    cudaFuncAttributeMaxDynamicSharedMemorySize, smemS);

    prep_kernel<<<48, 256>>>(W1a, W1b, W2a, W2b, (const unsigned int*)m1);
    aggregate_kernel<<<2 * BN_, 256>>>(nf, rel, nb1, rl1, m1, nb2, rl2, m2, self_);
    fused_proj_kernel<<<dim3(64, 1, 2), 256, FPROJ_SMEM>>>(b1a, b2a, b1b, b2b);
    sim_lse_kernel<<<dim3(32, 32), 256, smemS>>>();
    loss_kernel<<<1, 256>>>((float*)d_out);
}